// round 7
// baseline (speedup 1.0000x reference)
#include <cuda_runtime.h>
#include <math.h>

// HyperbolicMLR: logits[b,c] = scale_c * asinh( cf_c * dot(mob,a_c) / (1 - k*|mob|^2) )
// with mob collapsed to scalar algebra over three dot products.
// B=2048, C=1000, D=64 fp32.

#define K_CURV 0.1f
#define SQRT_K 0.31622776601683794f
#define CPAD   1024   // padded class count
#define DDIM   64

// ---- scratch (allocation-free: __device__ globals) ----
__device__ __align__(16) static float g_Pt[DDIM * CPAD];   // p_poin transposed [d][c]
__device__ __align__(16) static float g_At[DDIM * CPAD];   // a_poin transposed [d][c]
__device__ __align__(16) static float g_Sx2[CPAD];         // |p_poin|^2
__device__ __align__(16) static float g_Spa[CPAD];         // dot(-p_poin, a_poin)
__device__ __align__(16) static float g_Ssc[CPAD];         // lam * a_norm / sqrt_k
__device__ __align__(16) static float g_Scf[CPAD];         // 2*sqrt_k / a_norm
__device__ __align__(16) static float g_y2[2048];          // |x_b|^2

// ---- packed f32x2 helpers (Blackwell FFMA2 via PTX) ----
__device__ __forceinline__ unsigned long long pack2(float a, float b) {
    unsigned long long r;
    asm("mov.b64 %0, {%1, %2};" : "=l"(r) : "f"(a), "f"(b));
    return r;
}
__device__ __forceinline__ float2 unpack2(unsigned long long v) {
    float2 r;
    asm("mov.b64 {%0, %1}, %2;" : "=f"(r.x), "=f"(r.y) : "l"(v));
    return r;
}
__device__ __forceinline__ void ffma2(unsigned long long& acc,
                                      unsigned long long a, unsigned long long b) {
    asm("fma.rn.f32x2 %0, %1, %2, %0;" : "+l"(acc) : "l"(a), "l"(b));
}

// ===================== prep 1: per-class constants (one warp / class) ==========
__global__ void hmlr_prep_class(const float* __restrict__ a_vals,
                                const float* __restrict__ p_vals, int C) {
    int gw   = (blockIdx.x * blockDim.x + threadIdx.x) >> 5;  // class id 0..1023
    int lane = threadIdx.x & 31;
    if (gw >= CPAD) return;
    int c = gw;

    float2 pv = make_float2(0.f, 0.f), av = make_float2(0.f, 0.f);
    if (c < C) {
        pv = *(const float2*)(p_vals + c * DDIM + lane * 2);
        av = *(const float2*)(a_vals + c * DDIM + lane * 2);
    }
    float psq = pv.x * pv.x + pv.y * pv.y;
#pragma unroll
    for (int o = 16; o; o >>= 1) psq += __shfl_xor_sync(0xffffffffu, psq, o);

    float pn  = fmaxf(sqrtf(psq), 1e-15f);
    float arg = SQRT_K * pn;
    float t   = tanhf(arg) / arg;              // exp0 map factor
    float ppx = t * pv.x, ppy = t * pv.y;      // p_poin
    float p2  = t * t * psq;                   // |p_poin|^2
    float fac = 1.f + K_CURV * p2;
    float apx = av.x * fac, apy = av.y * fac;  // a_poin

    // store transposed [d][c] so the main kernel's smem fill is coalesced
    g_Pt[(lane * 2 + 0) * CPAD + c] = ppx;
    g_Pt[(lane * 2 + 1) * CPAD + c] = ppy;
    g_At[(lane * 2 + 0) * CPAD + c] = apx;
    g_At[(lane * 2 + 1) * CPAD + c] = apy;

    float a2  = apx * apx + apy * apy;
    float pad = ppx * apx + ppy * apy;
#pragma unroll
    for (int o = 16; o; o >>= 1) {
        a2  += __shfl_xor_sync(0xffffffffu, a2,  o);
        pad += __shfl_xor_sync(0xffffffffu, pad, o);
    }
    if (lane == 0) {
        float an  = fmaxf(sqrtf(a2), 1e-15f);
        float lam = 2.f / (1.f - K_CURV * p2);
        g_Sx2[c] = p2;
        g_Spa[c] = -pad;                 // dot(mp, a_poin)
        g_Ssc[c] = lam * an / SQRT_K;    // scale
        g_Scf[c] = 2.f * SQRT_K / an;    // folds numer's 2*sqrt_k and denom's a_norm
    }
}

// ===================== prep 2: y2[b] = |x_b|^2 (one warp / row) ================
__global__ void hmlr_prep_y2(const float* __restrict__ x, int B) {
    int gw   = (blockIdx.x * blockDim.x + threadIdx.x) >> 5;
    int lane = threadIdx.x & 31;
    if (gw >= B) return;
    float2 v = *(const float2*)(x + gw * DDIM + lane * 2);
    float s = v.x * v.x + v.y * v.y;
#pragma unroll
    for (int o = 16; o; o >>= 1) s += __shfl_xor_sync(0xffffffffu, s, o);
    if (lane == 0) g_y2[gw] = s;
}

// ===================== main: 64x64 tile, 4x4 micro-tile, FFMA2 =================
__global__ void __launch_bounds__(256)
hmlr_main(const float* __restrict__ x, float* __restrict__ out, int B, int C) {
    // exactly 48KB static smem
    __shared__ __align__(16) float xs[DDIM * 64];  // x tile, [d][b^(d&60)] XOR-swizzled
    __shared__ __align__(16) float ps[DDIM * 64];  // p_poin tile [d][c]
    __shared__ __align__(16) float qs[DDIM * 64];  // a_poin tile [d][c]

    const int tid   = threadIdx.x;
    const int cBase = blockIdx.x * 64;
    const int bBase = blockIdx.y * 64;

    // --- fill x tile, transposing b-major -> d-major with XOR swizzle ---
    {
        const float4* Xv = (const float4*)(x + (size_t)bBase * DDIM);
#pragma unroll
        for (int it = 0; it < 4; ++it) {
            int lin = tid + it * 256;            // 0..1023 == r*16 + ch
            float4 v = Xv[lin];
            int r  = lin >> 4;                   // b row 0..63
            int ch = lin & 15;                   // d chunk
            int db = ch * 4;                     // d base (multiple of 4)
            int pb = r ^ db;                     // swizzled b column (db == db&60)
            xs[(db + 0) * 64 + pb] = v.x;
            xs[(db + 1) * 64 + pb] = v.y;
            xs[(db + 2) * 64 + pb] = v.z;
            xs[(db + 3) * 64 + pb] = v.w;
        }
        // --- class tiles: already d-major in scratch, straight vector copy ---
#pragma unroll
        for (int it = 0; it < 4; ++it) {
            int lin = tid + it * 256;
            int d  = lin >> 4;
            int ch = lin & 15;
            *(float4*)(ps + d * 64 + ch * 4) =
                *(const float4*)(g_Pt + d * CPAD + cBase + ch * 4);
            *(float4*)(qs + d * 64 + ch * 4) =
                *(const float4*)(g_At + d * CPAD + cBase + ch * 4);
        }
    }
    __syncthreads();

    const int tx = tid & 15;        // class group (16 distinct per warp)
    const int ty = tid >> 4;        // batch group (2 distinct per warp -> broadcast)
    const int b0 = ty * 4;
    const int c0 = tx * 4;

    unsigned long long axp[4][2], axa[4][2];
#pragma unroll
    for (int i = 0; i < 4; ++i) { axp[i][0] = axp[i][1] = 0ull; axa[i][0] = axa[i][1] = 0ull; }

#pragma unroll
    for (int d = 0; d < DDIM; ++d) {
        const float4 xv = *(const float4*)(xs + d * 64 + (b0 ^ (d & 60)));
        const ulonglong2 pv = *(const ulonglong2*)(ps + d * 64 + c0);
        const ulonglong2 av = *(const ulonglong2*)(qs + d * 64 + c0);
        unsigned long long xb0 = pack2(xv.x, xv.x);
        unsigned long long xb1 = pack2(xv.y, xv.y);
        unsigned long long xb2 = pack2(xv.z, xv.z);
        unsigned long long xb3 = pack2(xv.w, xv.w);
        ffma2(axp[0][0], xb0, pv.x); ffma2(axp[0][1], xb0, pv.y);
        ffma2(axa[0][0], xb0, av.x); ffma2(axa[0][1], xb0, av.y);
        ffma2(axp[1][0], xb1, pv.x); ffma2(axp[1][1], xb1, pv.y);
        ffma2(axa[1][0], xb1, av.x); ffma2(axa[1][1], xb1, av.y);
        ffma2(axp[2][0], xb2, pv.x); ffma2(axp[2][1], xb2, pv.y);
        ffma2(axa[2][0], xb2, av.x); ffma2(axa[2][1], xb2, av.y);
        ffma2(axp[3][0], xb3, pv.x); ffma2(axp[3][1], xb3, pv.y);
        ffma2(axa[3][0], xb3, av.x); ffma2(axa[3][1], xb3, av.y);
    }

    // --- epilogue: scalar mobius/asinh algebra, per-class constants from gmem ---
    float fxp[4][4], fxa[4][4];
#pragma unroll
    for (int i = 0; i < 4; ++i) {
        float2 u;
        u = unpack2(axp[i][0]); fxp[i][0] = u.x; fxp[i][1] = u.y;
        u = unpack2(axp[i][1]); fxp[i][2] = u.x; fxp[i][3] = u.y;
        u = unpack2(axa[i][0]); fxa[i][0] = u.x; fxa[i][1] = u.y;
        u = unpack2(axa[i][1]); fxa[i][2] = u.x; fxa[i][3] = u.y;
    }

    const int cg = cBase + c0;
    const float4 x2v = *(const float4*)(g_Sx2 + cg);
    const float4 pav = *(const float4*)(g_Spa + cg);
    const float4 scv = *(const float4*)(g_Ssc + cg);
    const float4 cfv = *(const float4*)(g_Scf + cg);
    const float x2a[4] = {x2v.x, x2v.y, x2v.z, x2v.w};
    const float paa[4] = {pav.x, pav.y, pav.z, pav.w};
    const float sca[4] = {scv.x, scv.y, scv.z, scv.w};
    const float cfa[4] = {cfv.x, cfv.y, cfv.z, cfv.w};
    const bool wr = (cg + 3) < C;   // C % 4 == 0: vectors are all-in or all-out

#pragma unroll
    for (int i = 0; i < 4; ++i) {
        const int bg = bBase + b0 + i;
        const float y2 = g_y2[bg];
        float4 r;
        float* rp = (float*)&r;
#pragma unroll
        for (int j = 0; j < 4; ++j) {
            float xy = -fxp[i][j];           // dot(mp, x)
            float xa =  fxa[i][j];           // dot(a_poin, x)
            float x2 = x2a[j];               // |mp|^2
            float twokxy = 2.f * K_CURV * xy;
            float A   = 1.f + twokxy + K_CURV * y2;
            float Bf  = 1.f - K_CURV * x2;
            float den = 1.f + twokxy + (K_CURV * K_CURV) * x2 * y2;
            float inv = 1.f / den;
            float dotma = (A * paa[j] + Bf * xa) * inv;
            float mob2  = (A * A * x2 + 2.f * A * Bf * xy + Bf * Bf * y2) * (inv * inv);
            float ratio = cfa[j] * dotma / (1.f - K_CURV * mob2);
            rp[j] = sca[j] * asinhf(ratio);
        }
        if (wr) *(float4*)(out + (size_t)bg * C + cg) = r;
    }
}

// ===================== launch ==================================================
extern "C" void kernel_launch(void* const* d_in, const int* in_sizes, int n_in,
                              void* d_out, int out_size) {
    const float* x = (const float*)d_in[0];
    const float* a = (const float*)d_in[1];
    const float* p = (const float*)d_in[2];
    float* out = (float*)d_out;
    const int B = in_sizes[0] / DDIM;   // 2048
    const int C = in_sizes[1] / DDIM;   // 1000

    // 1024 class-warps (padded), 128 threads/block
    hmlr_prep_class<<<(CPAD * 32) / 128, 128>>>(a, p, C);
    // one warp per batch row
    hmlr_prep_y2<<<(B * 32 + 255) / 256, 256>>>(x, B);
    // main: 16 x 32 tiles of 64x64
    dim3 grid((C + 63) / 64, B / 64);
    hmlr_main<<<grid, 256>>>(x, out, B, C);
}

// round 8
// speedup vs baseline: 1.1990x; 1.1990x over previous
#include <cuda_runtime.h>
#include <math.h>

// HyperbolicMLR fused single-kernel: per-class poincare prep + dual GEMM
// (dot(p_poin,x), dot(a_poin,x)) + mobius/asinh epilogue.
// B=2048, C=1000, D=64 fp32. Block tile: 128 b x 64 c, thread tile 8b x 4c, FFMA2.

#define K_CURV 0.1f
#define SQRT_K 0.31622776601683794f
#define DDIM   64

// dynamic smem layout (bytes)
#define SM_XS   0                      // x tile [d][b^ (d&60)]  64*128*4 = 32768
#define SM_PS   32768                  // p_poin [d][c ^ (d&60)] 64*64*4  = 16384
#define SM_QS   49152                  // a_poin [d][c ^ (d&60)] 64*64*4  = 16384
#define SM_X2   65536                  // |p_poin|^2      [64]
#define SM_PA   65792                  // dot(mp,a_poin)  [64]
#define SM_SC   66048                  // scale           [64]
#define SM_CF   66304                  // 2*sqrt_k/a_norm [64]
#define SM_Y2   66560                  // |x_b|^2         [128]
#define SM_TOTAL 67072

// ---- packed f32x2 helpers (Blackwell FFMA2 via PTX) ----
__device__ __forceinline__ unsigned long long pack2(float a, float b) {
    unsigned long long r;
    asm("mov.b64 %0, {%1, %2};" : "=l"(r) : "f"(a), "f"(b));
    return r;
}
__device__ __forceinline__ float2 unpack2(unsigned long long v) {
    float2 r;
    asm("mov.b64 {%0, %1}, %2;" : "=f"(r.x), "=f"(r.y) : "l"(v));
    return r;
}
__device__ __forceinline__ void ffma2(unsigned long long& acc,
                                      unsigned long long a, unsigned long long b) {
    asm("fma.rn.f32x2 %0, %1, %2, %0;" : "+l"(acc) : "l"(a), "l"(b));
}

__global__ void __launch_bounds__(256, 2)
hmlr_fused(const float* __restrict__ x,
           const float* __restrict__ a_vals,
           const float* __restrict__ p_vals,
           float* __restrict__ out, int B, int C) {
    extern __shared__ __align__(16) char smem[];
    float* xs   = (float*)(smem + SM_XS);
    float* ps   = (float*)(smem + SM_PS);
    float* qs   = (float*)(smem + SM_QS);
    float* s_x2 = (float*)(smem + SM_X2);
    float* s_pa = (float*)(smem + SM_PA);
    float* s_sc = (float*)(smem + SM_SC);
    float* s_cf = (float*)(smem + SM_CF);
    float* s_y2 = (float*)(smem + SM_Y2);

    const int tid   = threadIdx.x;
    const int cBase = blockIdx.x * 64;
    const int bBase = blockIdx.y * 128;

    // ================= phase 1a: x tile fill (transpose + swizzle) + y2 ========
    {
        const float4* Xv = (const float4*)(x + (size_t)bBase * DDIM);
#pragma unroll
        for (int it = 0; it < 8; ++it) {
            int lin = tid + it * 256;           // 0..2047 = r*16 + ch
            float4 v = Xv[lin];
            int r  = lin >> 4;                  // b row 0..127
            int ch = lin & 15;                  // d chunk
            int db = ch * 4;                    // d base, multiple of 4
            int pb = r ^ db;                    // swizzled column (db == db&60)
            xs[(db + 0) * 128 + pb] = v.x;
            xs[(db + 1) * 128 + pb] = v.y;
            xs[(db + 2) * 128 + pb] = v.z;
            xs[(db + 3) * 128 + pb] = v.w;
            // y2: reduce across the 16 lanes sharing row r (16-aligned groups)
            float s = v.x * v.x + v.y * v.y + v.z * v.z + v.w * v.w;
            s += __shfl_xor_sync(0xffffffffu, s, 8);
            s += __shfl_xor_sync(0xffffffffu, s, 4);
            s += __shfl_xor_sync(0xffffffffu, s, 2);
            s += __shfl_xor_sync(0xffffffffu, s, 1);
            if (ch == 0) s_y2[r] = s;
        }
    }

    // ================= phase 1b: class prep (quad of lanes per class) ==========
    {
        const int cl = tid >> 2;                // local class 0..63
        const int sq = tid & 3;                 // quad lane: d in [sq*16, sq*16+16)
        const int cc = cBase + cl;
        const bool valid = (cc < C);

        float P[16], A[16];
        if (valid) {
            const float4* pb4 = (const float4*)(p_vals + (size_t)cc * DDIM + sq * 16);
            const float4* ab4 = (const float4*)(a_vals + (size_t)cc * DDIM + sq * 16);
#pragma unroll
            for (int i = 0; i < 4; ++i) {
                float4 pv = pb4[i], av = ab4[i];
                P[i*4+0]=pv.x; P[i*4+1]=pv.y; P[i*4+2]=pv.z; P[i*4+3]=pv.w;
                A[i*4+0]=av.x; A[i*4+1]=av.y; A[i*4+2]=av.z; A[i*4+3]=av.w;
            }
        } else {
#pragma unroll
            for (int i = 0; i < 16; ++i) { P[i] = 0.f; A[i] = 0.f; }
        }

        float psq = 0.f;
#pragma unroll
        for (int i = 0; i < 16; ++i) psq += P[i] * P[i];
        psq += __shfl_xor_sync(0xffffffffu, psq, 1);
        psq += __shfl_xor_sync(0xffffffffu, psq, 2);

        float pn  = fmaxf(sqrtf(psq), 1e-15f);
        float arg = SQRT_K * pn;
        float t   = tanhf(arg) / arg;           // exp0 factor
        float p2  = t * t * psq;                // |p_poin|^2
        float fac = 1.f + K_CURV * p2;

        float a2 = 0.f, pad = 0.f;
#pragma unroll
        for (int i = 0; i < 16; ++i) {
            float pp = t * P[i];
            float ap = fac * A[i];
            P[i] = pp; A[i] = ap;
            a2  += ap * ap;
            pad += pp * ap;
        }
        a2  += __shfl_xor_sync(0xffffffffu, a2, 1);
        a2  += __shfl_xor_sync(0xffffffffu, a2, 2);
        pad += __shfl_xor_sync(0xffffffffu, pad, 1);
        pad += __shfl_xor_sync(0xffffffffu, pad, 2);

        if (sq == 0) {
            float an  = fmaxf(sqrtf(a2), 1e-15f);
            float lam = 2.f / (1.f - K_CURV * p2);
            s_x2[cl] = p2;
            s_pa[cl] = -pad;                    // dot(mp, a_poin)
            s_sc[cl] = lam * an / SQRT_K;       // scale
            s_cf[cl] = 2.f * SQRT_K / an;       // folded numer/denom consts
        }
        // store transposed + swizzled
#pragma unroll
        for (int i = 0; i < 16; ++i) {
            int d = sq * 16 + i;
            int col = cl ^ (d & 60);
            ps[d * 64 + col] = P[i];
            qs[d * 64 + col] = A[i];
        }
    }
    __syncthreads();

    // ================= phase 2: dual GEMM, 8b x 4c per thread ==================
    const int tx = tid & 15;        // class group
    const int ty = tid >> 4;        // batch group
    const int b0 = ty * 8;
    const int c0 = tx * 4;

    unsigned long long accp[8][2], acca[8][2];
#pragma unroll
    for (int i = 0; i < 8; ++i) { accp[i][0]=accp[i][1]=0ull; acca[i][0]=acca[i][1]=0ull; }

#pragma unroll 16
    for (int d = 0; d < DDIM; ++d) {
        const int m = d & 60;
        const float4 xv0 = *(const float4*)(xs + d * 128 + ( b0      ^ m));
        const float4 xv1 = *(const float4*)(xs + d * 128 + ((b0 + 4) ^ m));
        const ulonglong2 pv = *(const ulonglong2*)(ps + d * 64 + (c0 ^ m));
        const ulonglong2 av = *(const ulonglong2*)(qs + d * 64 + (c0 ^ m));
        unsigned long long xb[8];
        xb[0] = pack2(xv0.x, xv0.x); xb[1] = pack2(xv0.y, xv0.y);
        xb[2] = pack2(xv0.z, xv0.z); xb[3] = pack2(xv0.w, xv0.w);
        xb[4] = pack2(xv1.x, xv1.x); xb[5] = pack2(xv1.y, xv1.y);
        xb[6] = pack2(xv1.z, xv1.z); xb[7] = pack2(xv1.w, xv1.w);
#pragma unroll
        for (int i = 0; i < 8; ++i) {
            ffma2(accp[i][0], xb[i], pv.x); ffma2(accp[i][1], xb[i], pv.y);
            ffma2(acca[i][0], xb[i], av.x); ffma2(acca[i][1], xb[i], av.y);
        }
    }

    // ================= phase 3: epilogue ========================================
    const int cg = cBase + c0;
    const bool wr = (cg + 3) < C;               // C % 4 == 0: all-in or all-out
    float x2a[4], paa[4], sca[4], cfa[4];
#pragma unroll
    for (int j = 0; j < 4; ++j) {
        x2a[j] = s_x2[c0 + j];
        paa[j] = s_pa[c0 + j];
        sca[j] = s_sc[c0 + j];
        cfa[j] = s_cf[c0 + j];
    }

#pragma unroll
    for (int i = 0; i < 8; ++i) {
        const float y2 = s_y2[b0 + i];
        float xp[4], xa[4];
        float2 u;
        u = unpack2(accp[i][0]); xp[0] = u.x; xp[1] = u.y;
        u = unpack2(accp[i][1]); xp[2] = u.x; xp[3] = u.y;
        u = unpack2(acca[i][0]); xa[0] = u.x; xa[1] = u.y;
        u = unpack2(acca[i][1]); xa[2] = u.x; xa[3] = u.y;

        float4 r;
        float* rp = (float*)&r;
#pragma unroll
        for (int j = 0; j < 4; ++j) {
            float xy = -xp[j];                  // dot(mp, x)
            float x2 = x2a[j];                  // |mp|^2
            float twokxy = 2.f * K_CURV * xy;
            float Af  = 1.f + twokxy + K_CURV * y2;
            float Bf  = 1.f - K_CURV * x2;
            float den = 1.f + twokxy + (K_CURV * K_CURV) * x2 * y2;
            float inv = __frcp_rn(den);
            float dotma = (Af * paa[j] + Bf * xa[j]) * inv;
            float mob2  = (Af * Af * x2 + 2.f * Af * Bf * xy + Bf * Bf * y2) * (inv * inv);
            float ratio = cfa[j] * dotma * __frcp_rn(1.f - K_CURV * mob2);
            // fast asinh: sign(x) * log(|x| + sqrt(x^2+1))
            float tt = fabsf(ratio);
            float z  = __logf(tt + __fsqrt_rn(fmaf(tt, tt, 1.f)));
            rp[j] = sca[j] * copysignf(z, ratio);
        }
        if (wr) {
            const int bg = bBase + b0 + i;
            *(float4*)(out + (size_t)bg * C + cg) = r;
        }
    }
}

// ===================== launch ==================================================
extern "C" void kernel_launch(void* const* d_in, const int* in_sizes, int n_in,
                              void* d_out, int out_size) {
    const float* x = (const float*)d_in[0];
    const float* a = (const float*)d_in[1];
    const float* p = (const float*)d_in[2];
    float* out = (float*)d_out;
    const int B = in_sizes[0] / DDIM;   // 2048
    const int C = in_sizes[1] / DDIM;   // 1000

    cudaFuncSetAttribute(hmlr_fused, cudaFuncAttributeMaxDynamicSharedMemorySize, SM_TOTAL);
    dim3 grid((C + 63) / 64, B / 128);  // 16 x 16 = 256 blocks, single wave @ 2/SM
    hmlr_fused<<<grid, 256, SM_TOTAL>>>(x, a, p, out, B, C);
}